// round 1
// baseline (speedup 1.0000x reference)
#include <cuda_runtime.h>

// ---------------------------------------------------------------------------
// HybridGNN: 2x GCNConv(+ReLU+BN) -> global mean pool -> concat rdkit ->
//            MLP (Linear+ReLU+BN) x2 -> Linear -> [G]
// Shapes: N=100000, E=3200000, F=64, H=128, 2H=256, R=200, G=4096
// ---------------------------------------------------------------------------

namespace {
constexpr int F_DIM = 64;
constexpr int H1    = 128;
constexpr int HH    = 256;   // 2H
constexpr int RDK   = 200;
constexpr int ZD    = 456;   // 2H + R
constexpr int NMAX  = 100000;
constexpr int GMAX  = 4096;
}

// Scratch (device globals; no allocations allowed)
__device__ float g_dinv[NMAX];
__device__ float g_xw [(size_t)NMAX * HH];
__device__ float g_h  [(size_t)NMAX * HH];
__device__ float g_stats[2 * HH];
__device__ float g_pool[(size_t)GMAX * HH];
__device__ float g_cnt [GMAX];
__device__ float g_z   [(size_t)GMAX * ZD];
__device__ float g_z1  [(size_t)GMAX * HH];
__device__ float g_z2  [(size_t)GMAX * H1];

// Vectorized fp32 global reduction (sm_90+): 4 adds, one instruction, no return.
__device__ __forceinline__ void red4(float* p, float4 v) {
    asm volatile("red.global.add.v4.f32 [%0], {%1,%2,%3,%4};"
                 :: "l"(p), "f"(v.x), "f"(v.y), "f"(v.z), "f"(v.w)
                 : "memory");
}

// ---------------------------------------------------------------------------
// Small utility kernels
// ---------------------------------------------------------------------------
__global__ void k_fill(float* p, float v, int n) {
    int i = blockIdx.x * blockDim.x + threadIdx.x;
    if (i < n) p[i] = v;
}

__global__ void k_deg_edges(const int* __restrict__ col, float* __restrict__ deg, int E) {
    int i = blockIdx.x * blockDim.x + threadIdx.x;
    if (i < E) atomicAdd(&deg[col[i]], 1.0f);
}

__global__ void k_rsqrt_inplace(float* p, int n) {
    int i = blockIdx.x * blockDim.x + threadIdx.x;
    if (i < n) p[i] = rsqrtf(p[i]);
}

// ---------------------------------------------------------------------------
// Tiled fp32 GEMM: C[N,M] = A[N,K] @ B[K,M]  (+ optional bias+ReLU epilogue)
// threads = 256. Thread computes RT rows x 4 cols.
// ---------------------------------------------------------------------------
template <int M, int BR, bool BIAS_RELU>
__global__ void k_gemm(const float* __restrict__ A, const float* __restrict__ B,
                       const float* __restrict__ bias, float* __restrict__ C,
                       int N, int K) {
    constexpr int KT   = 16;
    constexpr int CGRP = M / 4;         // thread-columns (each covers 4 cols)
    constexpr int RGRP = 256 / CGRP;    // row groups
    constexpr int RT   = BR / RGRP;     // rows per thread
    static_assert(RT * RGRP == BR, "tile mismatch");

    __shared__ float Bs[KT][M];
    __shared__ float As[KT][BR];

    const int row0 = blockIdx.x * BR;
    const int tc   = threadIdx.x % CGRP;
    const int tr   = threadIdx.x / CGRP;
    const int c0   = tc * 4;
    const int r0   = tr * RT;

    float acc[RT][4];
#pragma unroll
    for (int r = 0; r < RT; r++)
#pragma unroll
        for (int j = 0; j < 4; j++) acc[r][j] = 0.0f;

    for (int k0 = 0; k0 < K; k0 += KT) {
        // Load B tile (coalesced over columns)
        for (int idx = threadIdx.x; idx < KT * M; idx += 256) {
            int kk = idx / M, c = idx % M;
            int k = k0 + kk;
            Bs[kk][c] = (k < K) ? B[(size_t)k * M + c] : 0.0f;
        }
        // Load A tile
        for (int idx = threadIdx.x; idx < KT * BR; idx += 256) {
            int r = idx / KT, kk = idx % KT;
            int k = k0 + kk, row = row0 + r;
            As[kk][r] = (k < K && row < N) ? A[(size_t)row * K + k] : 0.0f;
        }
        __syncthreads();

#pragma unroll
        for (int kk = 0; kk < KT; kk++) {
            float4 b = *(const float4*)&Bs[kk][c0];
            float a[RT];
#pragma unroll
            for (int r = 0; r < RT; r++) a[r] = As[kk][r0 + r];
#pragma unroll
            for (int r = 0; r < RT; r++) {
                acc[r][0] += a[r] * b.x;
                acc[r][1] += a[r] * b.y;
                acc[r][2] += a[r] * b.z;
                acc[r][3] += a[r] * b.w;
            }
        }
        __syncthreads();
    }

    float4 bv = make_float4(0.f, 0.f, 0.f, 0.f);
    if constexpr (BIAS_RELU) bv = *(const float4*)&bias[c0];

#pragma unroll
    for (int r = 0; r < RT; r++) {
        int row = row0 + r0 + r;
        if (row < N) {
            float4 v = make_float4(acc[r][0], acc[r][1], acc[r][2], acc[r][3]);
            if constexpr (BIAS_RELU) {
                v.x = fmaxf(v.x + bv.x, 0.f);
                v.y = fmaxf(v.y + bv.y, 0.f);
                v.z = fmaxf(v.z + bv.z, 0.f);
                v.w = fmaxf(v.w + bv.w, 0.f);
            }
            *(float4*)&C[(size_t)row * M + c0] = v;
        }
    }
}

// ---------------------------------------------------------------------------
// GCN aggregation: self-loop init (h = xw * dinv^2) + edge scatter
// ---------------------------------------------------------------------------
template <int M>
__global__ void k_selfloop(const float* __restrict__ xw, const float* __restrict__ dinv,
                           float* __restrict__ h, int N) {
    size_t i = (size_t)blockIdx.x * blockDim.x + threadIdx.x;  // over N*M/4
    size_t total = (size_t)N * (M / 4);
    if (i >= total) return;
    int n = (int)(i / (M / 4));
    float d = dinv[n];
    float s = d * d;
    float4 v = ((const float4*)xw)[i];
    v.x *= s; v.y *= s; v.z *= s; v.w *= s;
    ((float4*)h)[i] = v;
}

// One warp per edge; lane handles M/128 float4 chunks.
template <int M>
__global__ void k_edge_agg(const int* __restrict__ row, const int* __restrict__ col,
                           const float* __restrict__ dinv,
                           const float* __restrict__ xw, float* __restrict__ h, int E) {
    int warp = (blockIdx.x * blockDim.x + threadIdx.x) >> 5;
    int lane = threadIdx.x & 31;
    if (warp >= E) return;
    int r = row[warp];     // uniform across warp (L1 broadcast)
    int c = col[warp];
    float nrm = dinv[r] * dinv[c];
    const float4* src = (const float4*)(xw + (size_t)r * M);
    float* dst = h + (size_t)c * M;
#pragma unroll
    for (int j = 0; j < M / 128; j++) {
        int f4 = lane + j * 32;
        float4 v = src[f4];
        v.x *= nrm; v.y *= nrm; v.z *= nrm; v.w *= nrm;
        red4(dst + f4 * 4, v);
    }
}

// ---------------------------------------------------------------------------
// BatchNorm (over rows): stats pass (optionally fused bias+ReLU in-place), apply
// ---------------------------------------------------------------------------
template <int M, bool FUSE_BIAS_RELU>
__global__ void k_bn_stats(float* __restrict__ h, const float* __restrict__ bias,
                           float* __restrict__ stats, int N) {
    int f = threadIdx.x;  // blockDim == M
    float b = 0.0f;
    if constexpr (FUSE_BIAS_RELU) b = bias[f];
    float s = 0.f, sq = 0.f;
    for (int n = blockIdx.x; n < N; n += gridDim.x) {
        size_t idx = (size_t)n * M + f;
        float v = h[idx];
        if constexpr (FUSE_BIAS_RELU) {
            v = fmaxf(v + b, 0.0f);
            h[idx] = v;
        }
        s += v;
        sq += v * v;
    }
    atomicAdd(&stats[f], s);
    atomicAdd(&stats[M + f], sq);
}

template <int M>
__global__ void k_bn_apply(float* __restrict__ h, const float* __restrict__ stats,
                           const float* __restrict__ gamma, const float* __restrict__ beta,
                           int N) {
    size_t i = (size_t)blockIdx.x * blockDim.x + threadIdx.x;
    if (i >= (size_t)N * M) return;
    int f = (int)(i % M);
    float inv_n = 1.0f / (float)N;
    float mu = stats[f] * inv_n;
    float var = stats[M + f] * inv_n - mu * mu;
    float sc = gamma[f] * rsqrtf(var + 1e-5f);
    h[i] = (h[i] - mu) * sc + beta[f];
}

// ---------------------------------------------------------------------------
// Global mean pool + concat with rdkit features
// ---------------------------------------------------------------------------
__global__ void k_pool_add(const float* __restrict__ h, const int* __restrict__ batch,
                           float* __restrict__ pool, float* __restrict__ cnt, int N) {
    size_t t = (size_t)blockIdx.x * blockDim.x + threadIdx.x;  // over N*(HH/4)
    if (t >= (size_t)N * (HH / 4)) return;
    int n  = (int)(t >> 6);         // HH/4 = 64
    int f4 = (int)(t & 63);
    int g = batch[n];
    float4 v = ((const float4*)(h + (size_t)n * HH))[f4];
    red4(pool + (size_t)g * HH + f4 * 4, v);
    if (f4 == 0) atomicAdd(&cnt[g], 1.0f);
}

__global__ void k_concat(const float* __restrict__ pool, const float* __restrict__ cnt,
                         const float* __restrict__ rdkit, float* __restrict__ z, int G) {
    int t = blockIdx.x * blockDim.x + threadIdx.x;
    if (t >= G * ZD) return;
    int g = t / ZD, f = t % ZD;
    float out;
    if (f < HH) out = pool[(size_t)g * HH + f] / fmaxf(cnt[g], 1.0f);
    else        out = rdkit[(size_t)g * RDK + (f - HH)];
    z[t] = out;
}

// ---------------------------------------------------------------------------
// Final projection: out[g] = z2[g,:] . mW3 + mb3
// ---------------------------------------------------------------------------
__global__ void k_final(const float* __restrict__ z2, const float* __restrict__ w,
                        const float* __restrict__ b, float* __restrict__ out, int G) {
    int warp = (blockIdx.x * blockDim.x + threadIdx.x) >> 5;
    int lane = threadIdx.x & 31;
    if (warp >= G) return;
    const float* zr = z2 + (size_t)warp * H1;
    float s = zr[lane] * w[lane] + zr[lane + 32] * w[lane + 32] +
              zr[lane + 64] * w[lane + 64] + zr[lane + 96] * w[lane + 96];
#pragma unroll
    for (int off = 16; off > 0; off >>= 1)
        s += __shfl_down_sync(0xffffffffu, s, off);
    if (lane == 0) out[warp] = s + b[0];
}

// ---------------------------------------------------------------------------
// Launch
// ---------------------------------------------------------------------------
extern "C" void kernel_launch(void* const* d_in, const int* in_sizes, int n_in,
                              void* d_out, int out_size) {
    const float* x      = (const float*)d_in[0];
    const int*   ei     = (const int*)d_in[1];
    const int*   batch  = (const int*)d_in[2];
    const float* rdkit  = (const float*)d_in[3];
    const float* W1  = (const float*)d_in[4];
    const float* b1  = (const float*)d_in[5];
    const float* gm1 = (const float*)d_in[6];
    const float* be1 = (const float*)d_in[7];
    const float* W2  = (const float*)d_in[8];
    const float* b2  = (const float*)d_in[9];
    const float* gm2 = (const float*)d_in[10];
    const float* be2 = (const float*)d_in[11];
    const float* mW1 = (const float*)d_in[12];
    const float* mb1 = (const float*)d_in[13];
    const float* mg1 = (const float*)d_in[14];
    const float* mbe1= (const float*)d_in[15];
    const float* mW2 = (const float*)d_in[16];
    const float* mb2 = (const float*)d_in[17];
    const float* mg2 = (const float*)d_in[18];
    const float* mbe2= (const float*)d_in[19];
    const float* mW3 = (const float*)d_in[20];
    const float* mb3 = (const float*)d_in[21];
    float* out = (float*)d_out;

    const int N = in_sizes[2];
    const int E = in_sizes[1] / 2;
    const int G = in_sizes[3] / RDK;
    const int* row = ei;
    const int* col = ei + E;

    float *dinv, *xw, *h, *stats, *pool, *cnt, *z, *z1, *z2;
    cudaGetSymbolAddress((void**)&dinv,  g_dinv);
    cudaGetSymbolAddress((void**)&xw,    g_xw);
    cudaGetSymbolAddress((void**)&h,     g_h);
    cudaGetSymbolAddress((void**)&stats, g_stats);
    cudaGetSymbolAddress((void**)&pool,  g_pool);
    cudaGetSymbolAddress((void**)&cnt,   g_cnt);
    cudaGetSymbolAddress((void**)&z,     g_z);
    cudaGetSymbolAddress((void**)&z1,    g_z1);
    cudaGetSymbolAddress((void**)&z2,    g_z2);

    auto cdiv = [](long long a, long long b) { return (int)((a + b - 1) / b); };

    // --- degree / dinv (self loops counted as +1) ---
    k_fill<<<cdiv(N, 256), 256>>>(dinv, 1.0f, N);
    k_deg_edges<<<cdiv(E, 256), 256>>>(col, dinv, E);
    k_rsqrt_inplace<<<cdiv(N, 256), 256>>>(dinv, N);

    // --- layer 1: xw = x @ W1 ; h = aggregate ; +b1, ReLU, BN ---
    k_gemm<H1, 64, false><<<cdiv(N, 64), 256>>>(x, W1, nullptr, xw, N, F_DIM);
    k_selfloop<H1><<<cdiv((long long)N * (H1 / 4), 256), 256>>>(xw, dinv, h, N);
    k_edge_agg<H1><<<cdiv((long long)E * 32, 256), 256>>>(row, col, dinv, xw, h, E);
    k_fill<<<1, 256>>>(stats, 0.0f, 2 * H1);
    k_bn_stats<H1, true><<<512, H1>>>(h, b1, stats, N);
    k_bn_apply<H1><<<cdiv((long long)N * H1, 256), 256>>>(h, stats, gm1, be1, N);

    // --- layer 2: xw = h @ W2 ; h = aggregate ; +b2, ReLU, BN ---
    k_gemm<HH, 32, false><<<cdiv(N, 32), 256>>>(h, W2, nullptr, xw, N, H1);
    k_selfloop<HH><<<cdiv((long long)N * (HH / 4), 256), 256>>>(xw, dinv, h, N);
    k_edge_agg<HH><<<cdiv((long long)E * 32, 256), 256>>>(row, col, dinv, xw, h, E);
    k_fill<<<2, 256>>>(stats, 0.0f, 2 * HH);
    k_bn_stats<HH, true><<<512, HH>>>(h, b2, stats, N);
    k_bn_apply<HH><<<cdiv((long long)N * HH, 256), 256>>>(h, stats, gm2, be2, N);

    // --- global mean pool + concat rdkit ---
    k_fill<<<cdiv((long long)G * HH, 256), 256>>>(pool, 0.0f, G * HH);
    k_fill<<<cdiv(G, 256), 256>>>(cnt, 0.0f, G);
    k_pool_add<<<cdiv((long long)N * (HH / 4), 256), 256>>>(h, batch, pool, cnt, N);
    k_concat<<<cdiv((long long)G * ZD, 256), 256>>>(pool, cnt, rdkit, z, G);

    // --- MLP head ---
    k_gemm<HH, 32, true><<<cdiv(G, 32), 256>>>(z, mW1, mb1, z1, G, ZD);
    k_fill<<<2, 256>>>(stats, 0.0f, 2 * HH);
    k_bn_stats<HH, false><<<256, HH>>>(z1, nullptr, stats, G);
    k_bn_apply<HH><<<cdiv((long long)G * HH, 256), 256>>>(z1, stats, mg1, mbe1, G);

    k_gemm<H1, 64, true><<<cdiv(G, 64), 256>>>(z1, mW2, mb2, z2, G, HH);
    k_fill<<<1, 256>>>(stats, 0.0f, 2 * H1);
    k_bn_stats<H1, false><<<256, H1>>>(z2, nullptr, stats, G);
    k_bn_apply<H1><<<cdiv((long long)G * H1, 256), 256>>>(z2, stats, mg2, mbe2, G);

    k_final<<<cdiv((long long)G * 32, 256), 256>>>(z2, mW3, mb3, out, G);
}

// round 2
// speedup vs baseline: 1.5619x; 1.5619x over previous
#include <cuda_runtime.h>

// ---------------------------------------------------------------------------
// HybridGNN: 2x GCNConv(+ReLU+BN) -> global mean pool -> concat rdkit ->
//            MLP (Linear+ReLU+BN) x2 -> Linear -> [G]
// Key optimization: GCN is linear, so aggregate FIRST, then GEMM:
//     Â (X W) == (Â X) W      (halves per-edge payload in both layers)
// ---------------------------------------------------------------------------

namespace {
constexpr int F_DIM = 64;
constexpr int H1    = 128;
constexpr int HH    = 256;   // 2H
constexpr int RDK   = 200;
constexpr int ZD    = 456;   // 2H + R
constexpr int NMAX  = 100000;
constexpr int GMAX  = 4096;
}

// Scratch (device globals; no allocations allowed)
__device__ float g_dinv[NMAX];
__device__ float g_agg[(size_t)NMAX * H1];   // agg buffer (max width 128)
__device__ float g_h  [(size_t)NMAX * HH];   // hidden activations (max width 256)
__device__ float g_stats[2 * HH];
__device__ float g_pool[(size_t)GMAX * HH];
__device__ float g_cnt [GMAX];
__device__ float g_z   [(size_t)GMAX * ZD];
__device__ float g_z1  [(size_t)GMAX * HH];
__device__ float g_z2  [(size_t)GMAX * H1];

// Vectorized fp32 global reduction (sm_90+): 4 adds, one instruction, no return.
__device__ __forceinline__ void red4(float* p, float4 v) {
    asm volatile("red.global.add.v4.f32 [%0], {%1,%2,%3,%4};"
                 :: "l"(p), "f"(v.x), "f"(v.y), "f"(v.z), "f"(v.w)
                 : "memory");
}

// ---------------------------------------------------------------------------
// Small utility kernels
// ---------------------------------------------------------------------------
__global__ void k_fill(float* p, float v, int n) {
    int i = blockIdx.x * blockDim.x + threadIdx.x;
    if (i < n) p[i] = v;
}

__global__ void k_deg_edges(const int* __restrict__ col, float* __restrict__ deg, int E) {
    int i = blockIdx.x * blockDim.x + threadIdx.x;
    if (i < E) atomicAdd(&deg[col[i]], 1.0f);
}

__global__ void k_rsqrt_inplace(float* p, int n) {
    int i = blockIdx.x * blockDim.x + threadIdx.x;
    if (i < n) p[i] = rsqrtf(p[i]);
}

// ---------------------------------------------------------------------------
// SGEMM: C[N,M] = A[N,K] @ B[K,M]  (+ optional bias + ReLU epilogue)
// 128x128 block tile, 256 threads, 8x8 per thread, KT=16.
// Requires M % 128 == 0, K % 4 == 0. blockIdx.y covers column tiles.
// ---------------------------------------------------------------------------
template <bool BIAS_RELU>
__launch_bounds__(256, 2)
__global__ void k_gemm128(const float* __restrict__ A, const float* __restrict__ B,
                          const float* __restrict__ bias, float* __restrict__ C,
                          int N, int K, int M) {
    constexpr int BM = 128, BN = 128, KT = 16;
    __shared__ float As[KT][BM];
    __shared__ float Bs[KT][BN];

    const int row0 = blockIdx.x * BM;
    const int colT = blockIdx.y * BN;
    const int tx   = threadIdx.x;
    const int tcol = tx & 15;     // 16 thread-cols
    const int trow = tx >> 4;     // 16 thread-rows
    const int c0   = colT + tcol * 8;
    const int r0   = row0 + trow * 8;

    float acc[8][8];
#pragma unroll
    for (int r = 0; r < 8; r++)
#pragma unroll
        for (int c = 0; c < 8; c++) acc[r][c] = 0.0f;

    for (int k0 = 0; k0 < K; k0 += KT) {
        // Load B tile: KT x BN (float4, coalesced over columns)
#pragma unroll
        for (int i = 0; i < 2; i++) {
            int idx = tx + i * 256;          // over 512 float4
            int kk  = idx >> 5;              // BN/4 = 32
            int cq  = idx & 31;
            int k   = k0 + kk;
            float4 v = make_float4(0.f, 0.f, 0.f, 0.f);
            if (k < K) v = *(const float4*)&B[(size_t)k * M + colT + cq * 4];
            *(float4*)&Bs[kk][cq * 4] = v;
        }
        // Load A tile (transposed into As[kk][r]); float4 along K
#pragma unroll
        for (int i = 0; i < 2; i++) {
            int idx = tx + i * 256;          // over 512 float4
            int r   = idx >> 2;              // KT/4 = 4 float4 per row
            int kq  = idx & 3;
            int row = row0 + r;
            int k   = k0 + kq * 4;
            float4 v = make_float4(0.f, 0.f, 0.f, 0.f);
            if (row < N) {
                if (k + 3 < K) {
                    v = *(const float4*)&A[(size_t)row * K + k];
                } else {
                    float t0 = (k + 0 < K) ? A[(size_t)row * K + k + 0] : 0.f;
                    float t1 = (k + 1 < K) ? A[(size_t)row * K + k + 1] : 0.f;
                    float t2 = (k + 2 < K) ? A[(size_t)row * K + k + 2] : 0.f;
                    float t3 = (k + 3 < K) ? A[(size_t)row * K + k + 3] : 0.f;
                    v = make_float4(t0, t1, t2, t3);
                }
            }
            As[kq * 4 + 0][r] = v.x;
            As[kq * 4 + 1][r] = v.y;
            As[kq * 4 + 2][r] = v.z;
            As[kq * 4 + 3][r] = v.w;
        }
        __syncthreads();

#pragma unroll
        for (int kk = 0; kk < KT; kk++) {
            float a[8], b[8];
            *(float4*)&a[0] = *(const float4*)&As[kk][trow * 8];
            *(float4*)&a[4] = *(const float4*)&As[kk][trow * 8 + 4];
            *(float4*)&b[0] = *(const float4*)&Bs[kk][tcol * 8];
            *(float4*)&b[4] = *(const float4*)&Bs[kk][tcol * 8 + 4];
#pragma unroll
            for (int r = 0; r < 8; r++)
#pragma unroll
                for (int c = 0; c < 8; c++)
                    acc[r][c] += a[r] * b[c];
        }
        __syncthreads();
    }

    float bv[8];
    if constexpr (BIAS_RELU) {
        *(float4*)&bv[0] = *(const float4*)&bias[c0];
        *(float4*)&bv[4] = *(const float4*)&bias[c0 + 4];
    }

#pragma unroll
    for (int r = 0; r < 8; r++) {
        int row = r0 + r;
        if (row < N) {
            if constexpr (BIAS_RELU) {
#pragma unroll
                for (int c = 0; c < 8; c++)
                    acc[r][c] = fmaxf(acc[r][c] + bv[c], 0.0f);
            }
            *(float4*)&C[(size_t)row * M + c0]     = *(float4*)&acc[r][0];
            *(float4*)&C[(size_t)row * M + c0 + 4] = *(float4*)&acc[r][4];
        }
    }
}

// ---------------------------------------------------------------------------
// GCN aggregation (on raw features, BEFORE the GEMM):
//   out[n] = dinv[n]^2 * src[n]  +  sum_{edges r->n} dinv[r]*dinv[n]*src[r]
// ---------------------------------------------------------------------------
template <int M>
__global__ void k_selfloop(const float* __restrict__ src, const float* __restrict__ dinv,
                           float* __restrict__ out, int N) {
    size_t i = (size_t)blockIdx.x * blockDim.x + threadIdx.x;  // over N*M/4
    if (i >= (size_t)N * (M / 4)) return;
    int n = (int)(i / (M / 4));
    float d = dinv[n];
    float s = d * d;
    float4 v = ((const float4*)src)[i];
    v.x *= s; v.y *= s; v.z *= s; v.w *= s;
    ((float4*)out)[i] = v;
}

// M/4 lanes per edge (16 for M=64, 32 for M=128), each lane one float4 RED.
template <int M>
__global__ void k_edge_agg(const int* __restrict__ row, const int* __restrict__ col,
                           const float* __restrict__ dinv,
                           const float* __restrict__ src, float* __restrict__ dst, int E) {
    constexpr int L = M / 4;
    int t = blockIdx.x * blockDim.x + threadIdx.x;
    int e = t / L;
    int l = t % L;
    if (e >= E) return;
    int r = row[e];
    int c = col[e];
    float nrm = dinv[r] * dinv[c];
    float4 v = ((const float4*)(src + (size_t)r * M))[l];
    v.x *= nrm; v.y *= nrm; v.z *= nrm; v.w *= nrm;
    red4(dst + (size_t)c * M + l * 4, v);
}

// ---------------------------------------------------------------------------
// BatchNorm (over rows): read-only stats pass, then apply in place
// ---------------------------------------------------------------------------
template <int M>
__global__ void k_bn_stats(const float* __restrict__ h, float* __restrict__ stats, int N) {
    int f = threadIdx.x;  // blockDim == M
    float s = 0.f, sq = 0.f;
    for (int n = blockIdx.x; n < N; n += gridDim.x) {
        float v = h[(size_t)n * M + f];
        s += v;
        sq += v * v;
    }
    atomicAdd(&stats[f], s);
    atomicAdd(&stats[M + f], sq);
}

template <int M>
__global__ void k_bn_apply(float* __restrict__ h, const float* __restrict__ stats,
                           const float* __restrict__ gamma, const float* __restrict__ beta,
                           int N) {
    size_t i = (size_t)blockIdx.x * blockDim.x + threadIdx.x;
    if (i >= (size_t)N * M) return;
    int f = (int)(i % M);
    float inv_n = 1.0f / (float)N;
    float mu = stats[f] * inv_n;
    float var = stats[M + f] * inv_n - mu * mu;
    float sc = gamma[f] * rsqrtf(var + 1e-5f);
    h[i] = (h[i] - mu) * sc + beta[f];
}

// ---------------------------------------------------------------------------
// Global mean pool + concat with rdkit features
// ---------------------------------------------------------------------------
__global__ void k_pool_add(const float* __restrict__ h, const int* __restrict__ batch,
                           float* __restrict__ pool, float* __restrict__ cnt, int N) {
    size_t t = (size_t)blockIdx.x * blockDim.x + threadIdx.x;  // over N*(HH/4)
    if (t >= (size_t)N * (HH / 4)) return;
    int n  = (int)(t >> 6);         // HH/4 = 64
    int f4 = (int)(t & 63);
    int g = batch[n];
    float4 v = ((const float4*)(h + (size_t)n * HH))[f4];
    red4(pool + (size_t)g * HH + f4 * 4, v);
    if (f4 == 0) atomicAdd(&cnt[g], 1.0f);
}

__global__ void k_concat(const float* __restrict__ pool, const float* __restrict__ cnt,
                         const float* __restrict__ rdkit, float* __restrict__ z, int G) {
    int t = blockIdx.x * blockDim.x + threadIdx.x;
    if (t >= G * ZD) return;
    int g = t / ZD, f = t % ZD;
    float out;
    if (f < HH) out = pool[(size_t)g * HH + f] / fmaxf(cnt[g], 1.0f);
    else        out = rdkit[(size_t)g * RDK + (f - HH)];
    z[t] = out;
}

// ---------------------------------------------------------------------------
// Final projection: out[g] = z2[g,:] . mW3 + mb3
// ---------------------------------------------------------------------------
__global__ void k_final(const float* __restrict__ z2, const float* __restrict__ w,
                        const float* __restrict__ b, float* __restrict__ out, int G) {
    int warp = (blockIdx.x * blockDim.x + threadIdx.x) >> 5;
    int lane = threadIdx.x & 31;
    if (warp >= G) return;
    const float* zr = z2 + (size_t)warp * H1;
    float s = zr[lane] * w[lane] + zr[lane + 32] * w[lane + 32] +
              zr[lane + 64] * w[lane + 64] + zr[lane + 96] * w[lane + 96];
#pragma unroll
    for (int off = 16; off > 0; off >>= 1)
        s += __shfl_down_sync(0xffffffffu, s, off);
    if (lane == 0) out[warp] = s + b[0];
}

// ---------------------------------------------------------------------------
// Launch
// ---------------------------------------------------------------------------
extern "C" void kernel_launch(void* const* d_in, const int* in_sizes, int n_in,
                              void* d_out, int out_size) {
    const float* x      = (const float*)d_in[0];
    const int*   ei     = (const int*)d_in[1];
    const int*   batch  = (const int*)d_in[2];
    const float* rdkit  = (const float*)d_in[3];
    const float* W1  = (const float*)d_in[4];
    const float* b1  = (const float*)d_in[5];
    const float* gm1 = (const float*)d_in[6];
    const float* be1 = (const float*)d_in[7];
    const float* W2  = (const float*)d_in[8];
    const float* b2  = (const float*)d_in[9];
    const float* gm2 = (const float*)d_in[10];
    const float* be2 = (const float*)d_in[11];
    const float* mW1 = (const float*)d_in[12];
    const float* mb1 = (const float*)d_in[13];
    const float* mg1 = (const float*)d_in[14];
    const float* mbe1= (const float*)d_in[15];
    const float* mW2 = (const float*)d_in[16];
    const float* mb2 = (const float*)d_in[17];
    const float* mg2 = (const float*)d_in[18];
    const float* mbe2= (const float*)d_in[19];
    const float* mW3 = (const float*)d_in[20];
    const float* mb3 = (const float*)d_in[21];
    float* out = (float*)d_out;

    const int N = in_sizes[2];
    const int E = in_sizes[1] / 2;
    const int G = in_sizes[3] / RDK;
    const int* row = ei;
    const int* col = ei + E;

    float *dinv, *agg, *h, *stats, *pool, *cnt, *z, *z1, *z2;
    cudaGetSymbolAddress((void**)&dinv,  g_dinv);
    cudaGetSymbolAddress((void**)&agg,   g_agg);
    cudaGetSymbolAddress((void**)&h,     g_h);
    cudaGetSymbolAddress((void**)&stats, g_stats);
    cudaGetSymbolAddress((void**)&pool,  g_pool);
    cudaGetSymbolAddress((void**)&cnt,   g_cnt);
    cudaGetSymbolAddress((void**)&z,     g_z);
    cudaGetSymbolAddress((void**)&z1,    g_z1);
    cudaGetSymbolAddress((void**)&z2,    g_z2);

    auto cdiv = [](long long a, long long b) { return (int)((a + b - 1) / b); };

    // --- degree / dinv (self loops counted as +1) ---
    k_fill<<<cdiv(N, 256), 256>>>(dinv, 1.0f, N);
    k_deg_edges<<<cdiv(E, 256), 256>>>(col, dinv, E);
    k_rsqrt_inplace<<<cdiv(N, 256), 256>>>(dinv, N);

    // --- layer 1: aggX = Â x  (64-wide) ; h1 = relu(aggX @ W1 + b1) ; BN ---
    k_selfloop<F_DIM><<<cdiv((long long)N * (F_DIM / 4), 256), 256>>>(x, dinv, agg, N);
    k_edge_agg<F_DIM><<<cdiv((long long)E * (F_DIM / 4), 256), 256>>>(row, col, dinv, x, agg, E);
    {
        dim3 grid(cdiv(N, 128), 1);
        k_gemm128<true><<<grid, 256>>>(agg, W1, b1, h, N, F_DIM, H1);
    }
    k_fill<<<1, 256>>>(stats, 0.0f, 2 * H1);
    k_bn_stats<H1><<<512, H1>>>(h, stats, N);
    k_bn_apply<H1><<<cdiv((long long)N * H1, 256), 256>>>(h, stats, gm1, be1, N);

    // --- layer 2: agg2 = Â h1b (128-wide) ; h2 = relu(agg2 @ W2 + b2) ; BN ---
    k_selfloop<H1><<<cdiv((long long)N * (H1 / 4), 256), 256>>>(h, dinv, agg, N);
    k_edge_agg<H1><<<cdiv((long long)E * (H1 / 4), 256), 256>>>(row, col, dinv, h, agg, E);
    {
        dim3 grid(cdiv(N, 128), HH / 128);
        k_gemm128<true><<<grid, 256>>>(agg, W2, b2, h, N, H1, HH);
    }
    k_fill<<<2, 256>>>(stats, 0.0f, 2 * HH);
    k_bn_stats<HH><<<512, HH>>>(h, stats, N);
    k_bn_apply<HH><<<cdiv((long long)N * HH, 256), 256>>>(h, stats, gm2, be2, N);

    // --- global mean pool + concat rdkit ---
    k_fill<<<cdiv((long long)G * HH, 256), 256>>>(pool, 0.0f, G * HH);
    k_fill<<<cdiv(G, 256), 256>>>(cnt, 0.0f, G);
    k_pool_add<<<cdiv((long long)N * (HH / 4), 256), 256>>>(h, batch, pool, cnt, N);
    k_concat<<<cdiv((long long)G * ZD, 256), 256>>>(pool, cnt, rdkit, z, G);

    // --- MLP head ---
    {
        dim3 grid(cdiv(G, 128), HH / 128);
        k_gemm128<true><<<grid, 256>>>(z, mW1, mb1, z1, G, ZD, HH);
    }
    k_fill<<<2, 256>>>(stats, 0.0f, 2 * HH);
    k_bn_stats<HH><<<256, HH>>>(z1, stats, G);
    k_bn_apply<HH><<<cdiv((long long)G * HH, 256), 256>>>(z1, stats, mg1, mbe1, G);

    {
        dim3 grid(cdiv(G, 128), 1);
        k_gemm128<true><<<grid, 256>>>(z1, mW2, mb2, z2, G, HH, H1);
    }
    k_fill<<<1, 256>>>(stats, 0.0f, 2 * H1);
    k_bn_stats<H1><<<256, H1>>>(z2, stats, G);
    k_bn_apply<H1><<<cdiv((long long)G * H1, 256), 256>>>(z2, stats, mg2, mbe2, G);

    k_final<<<cdiv((long long)G * 32, 256), 256>>>(z2, mW3, mb3, out, G);
}

// round 3
// speedup vs baseline: 2.2227x; 1.4231x over previous
#include <cuda_runtime.h>

// ---------------------------------------------------------------------------
// HybridGNN: 2x GCNConv(+ReLU+BN) -> global mean pool -> concat rdkit ->
//            MLP (Linear+ReLU+BN) x2 -> Linear -> [G]
// Optimizations:
//   * aggregate-then-GEMM:  Â (X W) == (Â X) W   (halves per-edge payload)
//   * per-launch padded-slot CSR (keyed by dst), reused by BOTH layers;
//     aggregation is register-accumulating GATHER (no atomics, 1x traffic)
// ---------------------------------------------------------------------------

namespace {
constexpr int F_DIM = 64;
constexpr int H1    = 128;
constexpr int HH    = 256;   // 2H
constexpr int RDK   = 200;
constexpr int ZD    = 456;   // 2H + R
constexpr int NMAX  = 100000;
constexpr int GMAX  = 4096;
constexpr int SLOTS = 160;   // max in-degree per node (Poisson(32): P(>=160)~0)
constexpr int OFCAP = 4096;  // overflow edge capacity (expected 0 used)
}

// Scratch (device globals; no allocations allowed)
__device__ float g_dinv[NMAX];
__device__ int   g_degc[NMAX];                     // degree / cursor
__device__ int   g_csr [(size_t)NMAX * SLOTS];     // src node per slot (64 MB)
__device__ int   g_ovf [OFCAP];
__device__ int   g_ovfcnt;
__device__ float g_agg[(size_t)NMAX * H1];
__device__ float g_h  [(size_t)NMAX * HH];
__device__ float g_stats[2 * HH];
__device__ float g_pool[(size_t)GMAX * HH];
__device__ float g_cnt [GMAX];
__device__ float g_z   [(size_t)GMAX * ZD];
__device__ float g_z1  [(size_t)GMAX * HH];
__device__ float g_z2  [(size_t)GMAX * H1];

__device__ __forceinline__ void red4(float* p, float4 v) {
    asm volatile("red.global.add.v4.f32 [%0], {%1,%2,%3,%4};"
                 :: "l"(p), "f"(v.x), "f"(v.y), "f"(v.z), "f"(v.w)
                 : "memory");
}

// ---------------------------------------------------------------------------
// Utility
// ---------------------------------------------------------------------------
__global__ void k_fill(float* p, float v, int n) {
    int i = blockIdx.x * blockDim.x + threadIdx.x;
    if (i < n) p[i] = v;
}
__global__ void k_fill_int(int* p, int v, int n) {
    int i = blockIdx.x * blockDim.x + threadIdx.x;
    if (i < n) p[i] = v;
}

// ---------------------------------------------------------------------------
// CSR build: slot = cursor[col]++; csr[col*SLOTS+slot] = row
// ---------------------------------------------------------------------------
__global__ void k_csr_build(const int* __restrict__ row, const int* __restrict__ col,
                            int* __restrict__ cursor, int* __restrict__ csr,
                            int* __restrict__ ovf, int* __restrict__ ovfcnt, int E) {
    int e = blockIdx.x * blockDim.x + threadIdx.x;
    if (e >= E) return;
    int c = col[e];
    int slot = atomicAdd(&cursor[c], 1);
    if (slot < SLOTS) {
        csr[(size_t)c * SLOTS + slot] = row[e];
    } else {
        int o = atomicAdd(ovfcnt, 1);
        if (o < OFCAP) ovf[o] = e;
    }
}

__global__ void k_dinv(const int* __restrict__ deg, float* __restrict__ dinv, int N) {
    int i = blockIdx.x * blockDim.x + threadIdx.x;
    if (i < N) dinv[i] = rsqrtf((float)deg[i] + 1.0f);
}

// ---------------------------------------------------------------------------
// Gather aggregation (warp per node), self-loop folded into accumulator init:
//   out[n] = dinv[n]^2 * src[n] + sum_{r in adj(n)} dinv[r]*dinv[n] * src[r]
// ---------------------------------------------------------------------------
template <int M>
__global__ void k_gather(const int* __restrict__ csr, const int* __restrict__ deg,
                         const float* __restrict__ dinv, const float* __restrict__ src,
                         float* __restrict__ out, int N) {
    int warp = (blockIdx.x * blockDim.x + threadIdx.x) >> 5;
    int lane = threadIdx.x & 31;
    if (warp >= N) return;
    const int n = warp;
    int d = deg[n];
    if (d > SLOTS) d = SLOTS;
    const float dn = dinv[n];
    const int* list = csr + (size_t)n * SLOTS;

    if constexpr (M == 128) {
        float4 acc = ((const float4*)(src + (size_t)n * M))[lane];
        float s = dn * dn;
        acc.x *= s; acc.y *= s; acc.z *= s; acc.w *= s;
        for (int base = 0; base < d; base += 32) {
            int li = base + lane;
            int idx = (li < d) ? list[li] : 0;
            float dr = (li < d) ? dinv[idx] : 0.0f;
            int m = min(32, d - base);
            int j = 0;
            for (; j + 1 < m; j += 2) {
                int   r0 = __shfl_sync(0xffffffffu, idx, j);
                float n0 = __shfl_sync(0xffffffffu, dr, j) * dn;
                int   r1 = __shfl_sync(0xffffffffu, idx, j + 1);
                float n1 = __shfl_sync(0xffffffffu, dr, j + 1) * dn;
                float4 v0 = ((const float4*)(src + (size_t)r0 * M))[lane];
                float4 v1 = ((const float4*)(src + (size_t)r1 * M))[lane];
                acc.x += n0 * v0.x + n1 * v1.x;
                acc.y += n0 * v0.y + n1 * v1.y;
                acc.z += n0 * v0.z + n1 * v1.z;
                acc.w += n0 * v0.w + n1 * v1.w;
            }
            if (j < m) {
                int   r0 = __shfl_sync(0xffffffffu, idx, j);
                float n0 = __shfl_sync(0xffffffffu, dr, j) * dn;
                float4 v0 = ((const float4*)(src + (size_t)r0 * M))[lane];
                acc.x += n0 * v0.x; acc.y += n0 * v0.y;
                acc.z += n0 * v0.z; acc.w += n0 * v0.w;
            }
        }
        ((float4*)(out + (size_t)n * M))[lane] = acc;
    } else {  // M == 64
        float2 acc = ((const float2*)(src + (size_t)n * M))[lane];
        float s = dn * dn;
        acc.x *= s; acc.y *= s;
        for (int base = 0; base < d; base += 32) {
            int li = base + lane;
            int idx = (li < d) ? list[li] : 0;
            float dr = (li < d) ? dinv[idx] : 0.0f;
            int m = min(32, d - base);
            int j = 0;
            for (; j + 1 < m; j += 2) {
                int   r0 = __shfl_sync(0xffffffffu, idx, j);
                float n0 = __shfl_sync(0xffffffffu, dr, j) * dn;
                int   r1 = __shfl_sync(0xffffffffu, idx, j + 1);
                float n1 = __shfl_sync(0xffffffffu, dr, j + 1) * dn;
                float2 v0 = ((const float2*)(src + (size_t)r0 * M))[lane];
                float2 v1 = ((const float2*)(src + (size_t)r1 * M))[lane];
                acc.x += n0 * v0.x + n1 * v1.x;
                acc.y += n0 * v0.y + n1 * v1.y;
            }
            if (j < m) {
                int   r0 = __shfl_sync(0xffffffffu, idx, j);
                float n0 = __shfl_sync(0xffffffffu, dr, j) * dn;
                float2 v0 = ((const float2*)(src + (size_t)r0 * M))[lane];
                acc.x += n0 * v0.x; acc.y += n0 * v0.y;
            }
        }
        ((float2*)(out + (size_t)n * M))[lane] = acc;
    }
}

// Overflow fallback (expected count 0): RED-scatter the dropped edges.
template <int M>
__global__ void k_overflow(const int* __restrict__ row, const int* __restrict__ col,
                           const int* __restrict__ ovf, const int* __restrict__ ovfcnt,
                           const float* __restrict__ dinv,
                           const float* __restrict__ src, float* __restrict__ dst) {
    int cnt = *ovfcnt;
    if (cnt > OFCAP) cnt = OFCAP;
    for (int i = threadIdx.x; i < cnt * (M / 4); i += blockDim.x) {
        int e = ovf[i / (M / 4)];
        int l = i % (M / 4);
        int r = row[e], c = col[e];
        float nrm = dinv[r] * dinv[c];
        float4 v = ((const float4*)(src + (size_t)r * M))[l];
        v.x *= nrm; v.y *= nrm; v.z *= nrm; v.w *= nrm;
        red4(dst + (size_t)c * M + l * 4, v);
    }
}

// ---------------------------------------------------------------------------
// SGEMM: C[N,M] = A[N,K] @ B[K,M]  (+ optional bias + ReLU epilogue)
// 128x128 block tile, 256 threads, 8x8 per thread, KT=16.
// ---------------------------------------------------------------------------
template <bool BIAS_RELU>
__launch_bounds__(256, 2)
__global__ void k_gemm128(const float* __restrict__ A, const float* __restrict__ B,
                          const float* __restrict__ bias, float* __restrict__ C,
                          int N, int K, int M) {
    constexpr int BM = 128, BN = 128, KT = 16;
    __shared__ float As[KT][BM];
    __shared__ float Bs[KT][BN];

    const int row0 = blockIdx.x * BM;
    const int colT = blockIdx.y * BN;
    const int tx   = threadIdx.x;
    const int tcol = tx & 15;
    const int trow = tx >> 4;
    const int c0   = colT + tcol * 8;
    const int r0   = row0 + trow * 8;

    float acc[8][8];
#pragma unroll
    for (int r = 0; r < 8; r++)
#pragma unroll
        for (int c = 0; c < 8; c++) acc[r][c] = 0.0f;

    for (int k0 = 0; k0 < K; k0 += KT) {
#pragma unroll
        for (int i = 0; i < 2; i++) {
            int idx = tx + i * 256;
            int kk  = idx >> 5;
            int cq  = idx & 31;
            int k   = k0 + kk;
            float4 v = make_float4(0.f, 0.f, 0.f, 0.f);
            if (k < K) v = *(const float4*)&B[(size_t)k * M + colT + cq * 4];
            *(float4*)&Bs[kk][cq * 4] = v;
        }
#pragma unroll
        for (int i = 0; i < 2; i++) {
            int idx = tx + i * 256;
            int r   = idx >> 2;
            int kq  = idx & 3;
            int row = row0 + r;
            int k   = k0 + kq * 4;
            float4 v = make_float4(0.f, 0.f, 0.f, 0.f);
            if (row < N) {
                if (k + 3 < K) {
                    v = *(const float4*)&A[(size_t)row * K + k];
                } else {
                    float t0 = (k + 0 < K) ? A[(size_t)row * K + k + 0] : 0.f;
                    float t1 = (k + 1 < K) ? A[(size_t)row * K + k + 1] : 0.f;
                    float t2 = (k + 2 < K) ? A[(size_t)row * K + k + 2] : 0.f;
                    float t3 = (k + 3 < K) ? A[(size_t)row * K + k + 3] : 0.f;
                    v = make_float4(t0, t1, t2, t3);
                }
            }
            As[kq * 4 + 0][r] = v.x;
            As[kq * 4 + 1][r] = v.y;
            As[kq * 4 + 2][r] = v.z;
            As[kq * 4 + 3][r] = v.w;
        }
        __syncthreads();

#pragma unroll
        for (int kk = 0; kk < KT; kk++) {
            float a[8], b[8];
            *(float4*)&a[0] = *(const float4*)&As[kk][trow * 8];
            *(float4*)&a[4] = *(const float4*)&As[kk][trow * 8 + 4];
            *(float4*)&b[0] = *(const float4*)&Bs[kk][tcol * 8];
            *(float4*)&b[4] = *(const float4*)&Bs[kk][tcol * 8 + 4];
#pragma unroll
            for (int r = 0; r < 8; r++)
#pragma unroll
                for (int c = 0; c < 8; c++)
                    acc[r][c] += a[r] * b[c];
        }
        __syncthreads();
    }

    float bv[8];
    if constexpr (BIAS_RELU) {
        *(float4*)&bv[0] = *(const float4*)&bias[c0];
        *(float4*)&bv[4] = *(const float4*)&bias[c0 + 4];
    }

#pragma unroll
    for (int r = 0; r < 8; r++) {
        int row = r0 + r;
        if (row < N) {
            if constexpr (BIAS_RELU) {
#pragma unroll
                for (int c = 0; c < 8; c++)
                    acc[r][c] = fmaxf(acc[r][c] + bv[c], 0.0f);
            }
            *(float4*)&C[(size_t)row * M + c0]     = *(float4*)&acc[r][0];
            *(float4*)&C[(size_t)row * M + c0 + 4] = *(float4*)&acc[r][4];
        }
    }
}

// ---------------------------------------------------------------------------
// BatchNorm: read-only stats pass + apply in place
// ---------------------------------------------------------------------------
template <int M>
__global__ void k_bn_stats(const float* __restrict__ h, float* __restrict__ stats, int N) {
    int f = threadIdx.x;
    float s = 0.f, sq = 0.f;
    for (int n = blockIdx.x; n < N; n += gridDim.x) {
        float v = h[(size_t)n * M + f];
        s += v;
        sq += v * v;
    }
    atomicAdd(&stats[f], s);
    atomicAdd(&stats[M + f], sq);
}

template <int M>
__global__ void k_bn_apply(float* __restrict__ h, const float* __restrict__ stats,
                           const float* __restrict__ gamma, const float* __restrict__ beta,
                           int N) {
    size_t i = (size_t)blockIdx.x * blockDim.x + threadIdx.x;
    if (i >= (size_t)N * M) return;
    int f = (int)(i % M);
    float inv_n = 1.0f / (float)N;
    float mu = stats[f] * inv_n;
    float var = stats[M + f] * inv_n - mu * mu;
    float sc = gamma[f] * rsqrtf(var + 1e-5f);
    h[i] = (h[i] - mu) * sc + beta[f];
}

// ---------------------------------------------------------------------------
// Global mean pool + concat with rdkit features
// ---------------------------------------------------------------------------
__global__ void k_pool_add(const float* __restrict__ h, const int* __restrict__ batch,
                           float* __restrict__ pool, float* __restrict__ cnt, int N) {
    size_t t = (size_t)blockIdx.x * blockDim.x + threadIdx.x;
    if (t >= (size_t)N * (HH / 4)) return;
    int n  = (int)(t >> 6);
    int f4 = (int)(t & 63);
    int g = batch[n];
    float4 v = ((const float4*)(h + (size_t)n * HH))[f4];
    red4(pool + (size_t)g * HH + f4 * 4, v);
    if (f4 == 0) atomicAdd(&cnt[g], 1.0f);
}

__global__ void k_concat(const float* __restrict__ pool, const float* __restrict__ cnt,
                         const float* __restrict__ rdkit, float* __restrict__ z, int G) {
    int t = blockIdx.x * blockDim.x + threadIdx.x;
    if (t >= G * ZD) return;
    int g = t / ZD, f = t % ZD;
    float out;
    if (f < HH) out = pool[(size_t)g * HH + f] / fmaxf(cnt[g], 1.0f);
    else        out = rdkit[(size_t)g * RDK + (f - HH)];
    z[t] = out;
}

// ---------------------------------------------------------------------------
// Final projection
// ---------------------------------------------------------------------------
__global__ void k_final(const float* __restrict__ z2, const float* __restrict__ w,
                        const float* __restrict__ b, float* __restrict__ out, int G) {
    int warp = (blockIdx.x * blockDim.x + threadIdx.x) >> 5;
    int lane = threadIdx.x & 31;
    if (warp >= G) return;
    const float* zr = z2 + (size_t)warp * H1;
    float s = zr[lane] * w[lane] + zr[lane + 32] * w[lane + 32] +
              zr[lane + 64] * w[lane + 64] + zr[lane + 96] * w[lane + 96];
#pragma unroll
    for (int off = 16; off > 0; off >>= 1)
        s += __shfl_down_sync(0xffffffffu, s, off);
    if (lane == 0) out[warp] = s + b[0];
}

// ---------------------------------------------------------------------------
// Launch
// ---------------------------------------------------------------------------
extern "C" void kernel_launch(void* const* d_in, const int* in_sizes, int n_in,
                              void* d_out, int out_size) {
    const float* x      = (const float*)d_in[0];
    const int*   ei     = (const int*)d_in[1];
    const int*   batch  = (const int*)d_in[2];
    const float* rdkit  = (const float*)d_in[3];
    const float* W1  = (const float*)d_in[4];
    const float* b1  = (const float*)d_in[5];
    const float* gm1 = (const float*)d_in[6];
    const float* be1 = (const float*)d_in[7];
    const float* W2  = (const float*)d_in[8];
    const float* b2  = (const float*)d_in[9];
    const float* gm2 = (const float*)d_in[10];
    const float* be2 = (const float*)d_in[11];
    const float* mW1 = (const float*)d_in[12];
    const float* mb1 = (const float*)d_in[13];
    const float* mg1 = (const float*)d_in[14];
    const float* mbe1= (const float*)d_in[15];
    const float* mW2 = (const float*)d_in[16];
    const float* mb2 = (const float*)d_in[17];
    const float* mg2 = (const float*)d_in[18];
    const float* mbe2= (const float*)d_in[19];
    const float* mW3 = (const float*)d_in[20];
    const float* mb3 = (const float*)d_in[21];
    float* out = (float*)d_out;

    const int N = in_sizes[2];
    const int E = in_sizes[1] / 2;
    const int G = in_sizes[3] / RDK;
    const int* row = ei;
    const int* col = ei + E;

    float *dinv, *agg, *h, *stats, *pool, *cnt, *z, *z1, *z2;
    int *degc, *csr, *ovf, *ovfcnt;
    cudaGetSymbolAddress((void**)&dinv,  g_dinv);
    cudaGetSymbolAddress((void**)&degc,  g_degc);
    cudaGetSymbolAddress((void**)&csr,   g_csr);
    cudaGetSymbolAddress((void**)&ovf,   g_ovf);
    cudaGetSymbolAddress((void**)&ovfcnt,g_ovfcnt);
    cudaGetSymbolAddress((void**)&agg,   g_agg);
    cudaGetSymbolAddress((void**)&h,     g_h);
    cudaGetSymbolAddress((void**)&stats, g_stats);
    cudaGetSymbolAddress((void**)&pool,  g_pool);
    cudaGetSymbolAddress((void**)&cnt,   g_cnt);
    cudaGetSymbolAddress((void**)&z,     g_z);
    cudaGetSymbolAddress((void**)&z1,    g_z1);
    cudaGetSymbolAddress((void**)&z2,    g_z2);

    auto cdiv = [](long long a, long long b) { return (int)((a + b - 1) / b); };

    // --- CSR build (shared by both layers) + dinv ---
    k_fill_int<<<cdiv(N, 256), 256>>>(degc, 0, N);
    k_fill_int<<<1, 32>>>(ovfcnt, 0, 1);
    k_csr_build<<<cdiv(E, 256), 256>>>(row, col, degc, csr, ovf, ovfcnt, E);
    k_dinv<<<cdiv(N, 256), 256>>>(degc, dinv, N);

    // --- layer 1: aggX = Â x (gather) ; h1 = relu(aggX @ W1 + b1) ; BN ---
    k_gather<F_DIM><<<cdiv((long long)N * 32, 256), 256>>>(csr, degc, dinv, x, agg, N);
    k_overflow<F_DIM><<<1, 256>>>(row, col, ovf, ovfcnt, dinv, x, agg);
    {
        dim3 grid(cdiv(N, 128), 1);
        k_gemm128<true><<<grid, 256>>>(agg, W1, b1, h, N, F_DIM, H1);
    }
    k_fill<<<1, 256>>>(stats, 0.0f, 2 * H1);
    k_bn_stats<H1><<<512, H1>>>(h, stats, N);
    k_bn_apply<H1><<<cdiv((long long)N * H1, 256), 256>>>(h, stats, gm1, be1, N);

    // --- layer 2: agg2 = Â h1 (gather) ; h2 = relu(agg2 @ W2 + b2) ; BN ---
    k_gather<H1><<<cdiv((long long)N * 32, 256), 256>>>(csr, degc, dinv, h, agg, N);
    k_overflow<H1><<<1, 256>>>(row, col, ovf, ovfcnt, dinv, h, agg);
    {
        dim3 grid(cdiv(N, 128), HH / 128);
        k_gemm128<true><<<grid, 256>>>(agg, W2, b2, h, N, H1, HH);
    }
    k_fill<<<2, 256>>>(stats, 0.0f, 2 * HH);
    k_bn_stats<HH><<<512, HH>>>(h, stats, N);
    k_bn_apply<HH><<<cdiv((long long)N * HH, 256), 256>>>(h, stats, gm2, be2, N);

    // --- global mean pool + concat rdkit ---
    k_fill<<<cdiv((long long)G * HH, 256), 256>>>(pool, 0.0f, G * HH);
    k_fill<<<cdiv(G, 256), 256>>>(cnt, 0.0f, G);
    k_pool_add<<<cdiv((long long)N * (HH / 4), 256), 256>>>(h, batch, pool, cnt, N);
    k_concat<<<cdiv((long long)G * ZD, 256), 256>>>(pool, cnt, rdkit, z, G);

    // --- MLP head ---
    {
        dim3 grid(cdiv(G, 128), HH / 128);
        k_gemm128<true><<<grid, 256>>>(z, mW1, mb1, z1, G, ZD, HH);
    }
    k_fill<<<2, 256>>>(stats, 0.0f, 2 * HH);
    k_bn_stats<HH><<<256, HH>>>(z1, stats, G);
    k_bn_apply<HH><<<cdiv((long long)G * HH, 256), 256>>>(z1, stats, mg1, mbe1, G);

    {
        dim3 grid(cdiv(G, 128), 1);
        k_gemm128<true><<<grid, 256>>>(z1, mW2, mb2, z2, G, HH, H1);
    }
    k_fill<<<1, 256>>>(stats, 0.0f, 2 * H1);
    k_bn_stats<H1><<<256, H1>>>(z2, stats, G);
    k_bn_apply<H1><<<cdiv((long long)G * H1, 256), 256>>>(z2, stats, mg2, mbe2, G);

    k_final<<<cdiv((long long)G * 32, 256), 256>>>(z2, mW3, mb3, out, G);
}